// round 11
// baseline (speedup 1.0000x reference)
#include <cuda_runtime.h>
#include <cuda_bf16.h>
#include <cstdint>

#define NROWS 8192
#define DIM   512
#define TM    128
#define TN    128
#define KC    64              // K chunk (bf16 elems): 128 B per row
#define NC    (DIM / KC)      // 8 chunks
#define NBLK  (NROWS / TM)    // 64
#define NTILES (NBLK * (NBLK + 1) / 2)   // 2080
#define STAGES 3
#define TILE_BYTES (128 * 128)           // 16384 per operand (swizzled, no pad)
#define STAGE_BYTES (2 * TILE_BYTES)     // 32768 (A then B)
#define GRID 296              // 148 SMs x 2 CTAs

#define INVT_LOG2E 20.609929155556620f   // log2(e)/0.07
#define LN2 0.69314718055994531f

// ---- scratch (__device__ globals; allocation-free rule) ----
__device__ __nv_bfloat16 g_ebf[NROWS * DIM];
__device__ float g_num[NROWS];
__device__ float g_den[NROWS];
__device__ int   g_lab[NROWS];
__device__ unsigned g_done;

// ---- dynamic smem layout ----
#define OFF_RN (STAGES * STAGE_BYTES)          // 98304
#define OFF_RD (OFF_RN + 512)
#define OFF_CN (OFF_RD + 512)
#define OFF_CD (OFF_CN + 512)
#define SMEM_BYTES (OFF_CD + 512)              // 100352 -> 2 CTAs/SM

// swizzled smem address: row-major 128B rows, 16B seg s XOR'd with row&7
#define SWADDR(base, r, s) ((base) + ((r) << 7) + ((((s) ^ ((r) & 7))) << 4))

// ============================ PTX helpers ============================
__device__ __forceinline__ uint32_t smem_u32(const void* p) {
    uint32_t a;
    asm("{ .reg .u64 t; cvta.to.shared.u64 t, %1; cvt.u32.u64 %0, t; }" : "=r"(a) : "l"(p));
    return a;
}
#define CPA(dst, src)  asm volatile("cp.async.cg.shared.global [%0], [%1], 16;" :: "r"(dst), "l"(src))
#define CPA_COMMIT()   asm volatile("cp.async.commit_group;" ::: "memory")
#define CPA_WAIT(n)    asm volatile("cp.async.wait_group %0;" :: "n"(n) : "memory")

__device__ __forceinline__ void ldmx4(uint32_t& r0, uint32_t& r1, uint32_t& r2, uint32_t& r3,
                                      uint32_t addr) {
    asm volatile("ldmatrix.sync.aligned.m8n8.x4.shared.b16 {%0,%1,%2,%3}, [%4];"
                 : "=r"(r0), "=r"(r1), "=r"(r2), "=r"(r3) : "r"(addr));
}
__device__ __forceinline__ void mma16816(float* d, const uint32_t* a, const uint32_t* b) {
    asm volatile(
        "mma.sync.aligned.m16n8k16.row.col.f32.bf16.bf16.f32 "
        "{%0,%1,%2,%3}, {%4,%5,%6,%7}, {%8,%9}, {%0,%1,%2,%3};"
        : "+f"(d[0]), "+f"(d[1]), "+f"(d[2]), "+f"(d[3])
        : "r"(a[0]), "r"(a[1]), "r"(a[2]), "r"(a[3]), "r"(b[0]), "r"(b[1]));
}
__device__ __forceinline__ float fast_exp2(float x) {
    float y;
    asm("ex2.approx.f32 %0, %1;" : "=f"(y) : "f"(x));
    return y;
}
__device__ __forceinline__ float fast_log(float x) {
    float y;
    asm("lg2.approx.f32 %0, %1;" : "=f"(y) : "f"(x));
    return y * LN2;
}

// cp.async one 64-wide K chunk (128B/row, swizzled) of A and B into a stage buffer
__device__ __forceinline__ void load_chunk(uint32_t s, const __nv_bfloat16* A,
                                           const __nv_bfloat16* B, int k0, int tid) {
    const uint32_t sa = s, sb = s + TILE_BYTES;
    #pragma unroll
    for (int i = 0; i < 4; i++) {
        const int idx = tid + i * 256;        // 0..1023
        const int r = idx >> 3, q = idx & 7;  // row 0..127, 16B seg 0..7
        CPA(SWADDR(sa, r, q), A + (size_t)r * DIM + k0 + q * 8);
        CPA(SWADDR(sb, r, q), B + (size_t)r * DIM + k0 + q * 8);
    }
}

__device__ __forceinline__ void tile_coords(int t, int& bi, int& bj) {
    int b = 0;
    while (t >= NBLK - b) { t -= NBLK - b; b++; }
    bi = b; bj = b + t;
}

// B fragments for one ks step (2 x ldmx4 -> 4 n-tiles)
__device__ __forceinline__ void load_b(uint32_t sb, int ks, int wn, int lane,
                                       uint32_t (&b)[4][2]) {
    #pragma unroll
    for (int p = 0; p < 2; p++) {
        const int nrow = wn * 32 + p * 16 + ((lane >> 4) << 3) + (lane & 7);
        const int seg = ks * 2 + ((lane >> 3) & 1);
        uint32_t r0, r1, r2, r3;
        ldmx4(r0, r1, r2, r3, SWADDR(sb, nrow, seg));
        b[2 * p][0] = r0; b[2 * p][1] = r1;
        b[2 * p + 1][0] = r2; b[2 * p + 1][1] = r3;
    }
}
// A fragment for one (ks, mt) (1 x ldmx4)
__device__ __forceinline__ void load_a(uint32_t sa, int ks, int mt, int wm, int lane,
                                       uint32_t (&a)[4]) {
    const int arow = wm * 64 + mt * 16 + (lane & 15);
    const int aseg = ks * 2 + (lane >> 4);
    ldmx4(a[0], a[1], a[2], a[3], SWADDR(sa, arow, aseg));
}

// ============================ Kernel 1: normalize + decode labels ============================
__global__ void normalize_kernel(const float* __restrict__ emb, const int* __restrict__ lab32) {
    const int row = blockIdx.x;
    const float* in = emb + (size_t)row * DIM;

    const int c = threadIdx.x * 4;
    float4 x = *(const float4*)(in + c);
    float ss = x.x * x.x + x.y * x.y + x.z * x.z + x.w * x.w;

    #pragma unroll
    for (int o = 16; o; o >>= 1) ss += __shfl_xor_sync(0xffffffffu, ss, o);

    __shared__ float red[4];
    if ((threadIdx.x & 31) == 0) red[threadIdx.x >> 5] = ss;
    __syncthreads();
    const float inv = rsqrtf(red[0] + red[1] + red[2] + red[3]);

    __nv_bfloat162 p0 = __floats2bfloat162_rn(x.x * inv, x.y * inv);
    __nv_bfloat162 p1 = __floats2bfloat162_rn(x.z * inv, x.w * inv);
    __nv_bfloat162* out = (__nv_bfloat162*)(g_ebf + (size_t)row * DIM + c);
    out[0] = p0; out[1] = p1;

    // label decode: 32 odd-word probes (in-bounds under either layout).
    if (threadIdx.x < 32) {
        const unsigned probe = __ballot_sync(0xffffffffu, lab32[2 * threadIdx.x + 1] != 0);
        if (threadIdx.x == 0)
            g_lab[row] = (probe == 0u) ? lab32[2 * row] : lab32[row];
    }
    if (threadIdx.x == 0) {
        g_num[row] = 0.0f; g_den[row] = 0.0f;
        if (row == 0) g_done = 0u;
    }
}

// ============================ Kernel 2: persistent mma.sync GEMM + epilogue + finalize ============================
__global__ __launch_bounds__(256, 2)
void sim_loss_mma(float* __restrict__ out) {
    extern __shared__ __align__(128) char SM[];
    const uint32_t sbase = smem_u32(SM);
    const int tid = threadIdx.x, wid = tid >> 5, lane = tid & 31;
    const int wm = wid >> 2, wn = wid & 3;   // warp grid 2 (M) x 4 (N)

    float* sRN = (float*)(SM + OFF_RN);
    float* sRD = (float*)(SM + OFF_RD);
    float* sCN = (float*)(SM + OFF_CN);
    float* sCD = (float*)(SM + OFF_CD);

    int t = blockIdx.x;
    int bi, bj;
    tile_coords(t, bi, bj);
    const __nv_bfloat16* Ag = g_ebf + (size_t)bi * TM * DIM;
    const __nv_bfloat16* Bg = g_ebf + (size_t)bj * TN * DIM;

    // prologue: chunks 0,1 of first tile into buffers 0,1
    load_chunk(sbase + 0 * STAGE_BYTES, Ag, Bg, 0, tid); CPA_COMMIT();
    load_chunk(sbase + 1 * STAGE_BYTES, Ag, Bg, KC, tid); CPA_COMMIT();
    int wbuf = 2;   // next buffer to write (cycles 0..2 across tiles)
    int rbuf = 0;   // buffer of current compute chunk

    float acc[4][4][4];
    #pragma unroll
    for (int i = 0; i < 4; i++)
        #pragma unroll
        for (int j = 0; j < 4; j++)
            #pragma unroll
            for (int v = 0; v < 4; v++) acc[i][j][v] = 0.0f;

    while (true) {
        const int rowBase = bi * TM, colBase = bj * TN;
        const bool offDiag = (bi != bj);

        const int tn = t + GRID;
        const bool hasNext = (tn < NTILES);
        const __nv_bfloat16 *An = Ag, *Bn = Bg;
        int nbi = bi, nbj = bj;
        if (hasNext) {
            tile_coords(tn, nbi, nbj);
            An = g_ebf + (size_t)nbi * TM * DIM;
            Bn = g_ebf + (size_t)nbj * TN * DIM;
        }

        // ---- mainloop: 8 chunks of K=64, 3-stage cycle, prefetch distance 2 ----
        #pragma unroll 1
        for (int c = 0; c < NC; c++) {
            if (c == NC - 1 && !hasNext) { CPA_WAIT(0); } else { CPA_WAIT(1); }
            __syncthreads();

            // prefetch chunk c+2 into the buffer consumed at iteration c-1
            const int pc = c + STAGES - 1;   // c + 2
            if (pc < NC) {
                load_chunk(sbase + wbuf * STAGE_BYTES, Ag, Bg, pc * KC, tid);
                CPA_COMMIT();
                wbuf = (wbuf + 1 == STAGES) ? 0 : wbuf + 1;
            } else if (hasNext && pc - NC < STAGES - 1) {
                load_chunk(sbase + wbuf * STAGE_BYTES, An, Bn, (pc - NC) * KC, tid);
                CPA_COMMIT();
                wbuf = (wbuf + 1 == STAGES) ? 0 : wbuf + 1;
            }

            const uint32_t sa = sbase + rbuf * STAGE_BYTES;
            const uint32_t sb = sa + TILE_BYTES;
            rbuf = (rbuf + 1 == STAGES) ? 0 : rbuf + 1;

            // fragment-double-buffered pipeline: B across ks, A across mt
            uint32_t bfr[2][4][2];
            uint32_t afr[2][4];
            load_b(sb, 0, wn, lane, bfr[0]);
            #pragma unroll
            for (int ks = 0; ks < 4; ks++) {
                const int cb = ks & 1;
                if (ks < 3) load_b(sb, ks + 1, wn, lane, bfr[cb ^ 1]);
                load_a(sa, ks, 0, wm, lane, afr[0]);
                #pragma unroll
                for (int mt = 0; mt < 4; mt++) {
                    const int ca = mt & 1;
                    if (mt < 3) load_a(sa, ks, mt + 1, wm, lane, afr[ca ^ 1]);
                    #pragma unroll
                    for (int nt = 0; nt < 4; nt++)
                        mma16816(acc[mt][nt], afr[ca], bfr[cb][nt]);
                }
            }
        }

        // ---- epilogue (next-tile chunks 0,1 already in flight) ----
        __syncthreads();
        if (tid < 128) { sRN[tid] = 0.0f; sRD[tid] = 0.0f; }
        else           { sCN[tid - 128] = 0.0f; sCD[tid - 128] = 0.0f; }
        __syncthreads();

        int liArr[8], ljArr[8];
        #pragma unroll
        for (int mt = 0; mt < 4; mt++)
            #pragma unroll
            for (int rh = 0; rh < 2; rh++)
                liArr[mt * 2 + rh] = g_lab[rowBase + wm * 64 + mt * 16 + rh * 8 + (lane >> 2)];
        #pragma unroll
        for (int nt = 0; nt < 4; nt++)
            #pragma unroll
            for (int ce = 0; ce < 2; ce++)
                ljArr[nt * 2 + ce] = g_lab[colBase + wn * 32 + nt * 8 + 2 * (lane & 3) + ce];

        // row pass: exp once; sign carries the v>0 predicate for the col pass
        #pragma unroll
        for (int mt = 0; mt < 4; mt++) {
            #pragma unroll
            for (int rh = 0; rh < 2; rh++) {
                const int rloc = wm * 64 + mt * 16 + rh * 8 + (lane >> 2);
                const int gi = rowBase + rloc;
                const int li = liArr[mt * 2 + rh];
                float rnum = 0.0f, rden = 0.0f;
                #pragma unroll
                for (int nt = 0; nt < 4; nt++) {
                    #pragma unroll
                    for (int ce = 0; ce < 2; ce++) {
                        const int cloc = wn * 32 + nt * 8 + 2 * (lane & 3) + ce;
                        const int gj = colBase + cloc;
                        const float v = acc[mt][nt][rh * 2 + ce];
                        const float e = fast_exp2(v * INVT_LOG2E);
                        const bool diag = (gi == gj);
                        const bool pos = !diag && (li == ljArr[nt * 2 + ce]) && (v > 0.0f);
                        rden += diag ? 0.0f : e;
                        rnum += pos ? e : 0.0f;
                        acc[mt][nt][rh * 2 + ce] = (v > 0.0f) ? e : -e;
                    }
                }
                rnum += __shfl_xor_sync(0xffffffffu, rnum, 1);
                rden += __shfl_xor_sync(0xffffffffu, rden, 1);
                rnum += __shfl_xor_sync(0xffffffffu, rnum, 2);
                rden += __shfl_xor_sync(0xffffffffu, rden, 2);
                if ((lane & 3) == 0) {
                    atomicAdd(&sRD[rloc], rden);
                    if (rnum != 0.0f) atomicAdd(&sRN[rloc], rnum);
                }
            }
        }
        if (offDiag) {
            #pragma unroll
            for (int nt = 0; nt < 4; nt++) {
                #pragma unroll
                for (int ce = 0; ce < 2; ce++) {
                    const int cloc = wn * 32 + nt * 8 + 2 * (lane & 3) + ce;
                    const int lj = ljArr[nt * 2 + ce];
                    float cnum = 0.0f, cden = 0.0f;
                    #pragma unroll
                    for (int mt = 0; mt < 4; mt++) {
                        #pragma unroll
                        for (int rh = 0; rh < 2; rh++) {
                            const float s = acc[mt][nt][rh * 2 + ce];
                            const float e = fabsf(s);
                            const bool pos = (liArr[mt * 2 + rh] == lj) && (s > 0.0f);
                            cden += e;
                            cnum += pos ? e : 0.0f;
                        }
                    }
                    cnum += __shfl_xor_sync(0xffffffffu, cnum, 4);
                    cden += __shfl_xor_sync(0xffffffffu, cden, 4);
                    cnum += __shfl_xor_sync(0xffffffffu, cnum, 8);
                    cden += __shfl_xor_sync(0xffffffffu, cden, 8);
                    cnum += __shfl_xor_sync(0xffffffffu, cnum, 16);
                    cden += __shfl_xor_sync(0xffffffffu, cden, 16);
                    if (lane < 4) {   // one writer per lane&3 group
                        atomicAdd(&sCD[cloc], cden);
                        if (cnum != 0.0f) atomicAdd(&sCN[cloc], cnum);
                    }
                }
            }
        }
        __syncthreads();

        if (tid < 128) {
            atomicAdd(&g_den[rowBase + tid], sRD[tid]);
            const float rn = sRN[tid];
            if (rn != 0.0f) atomicAdd(&g_num[rowBase + tid], rn);
        } else if (offDiag) {
            const int i = tid - 128;
            atomicAdd(&g_den[colBase + i], sCD[i]);
            const float cn = sCN[i];
            if (cn != 0.0f) atomicAdd(&g_num[colBase + i], cn);
        }

        #pragma unroll
        for (int i = 0; i < 4; i++)
            #pragma unroll
            for (int j = 0; j < 4; j++)
                #pragma unroll
                for (int v = 0; v < 4; v++) acc[i][j][v] = 0.0f;

        if (!hasNext) break;
        t = tn; bi = nbi; bj = nbj; Ag = An; Bg = Bn;
    }

    // ---- grid completion: last CTA computes the final loss ----
    __syncthreads();
    __threadfence();
    __shared__ int isLast;
    if (tid == 0) isLast = (atomicAdd(&g_done, 1u) == (unsigned)(gridDim.x - 1)) ? 1 : 0;
    __syncthreads();
    if (isLast) {
        float sum = 0.0f;
        int cnt = 0;
        for (int i = tid; i < NROWS; i += 256) {
            const float nu = g_num[i];
            const float de = g_den[i];
            if (nu > 0.0f && de > 0.0f) {
                sum += fast_log((de + 1e-8f) / nu);
                cnt++;
            }
        }
        #pragma unroll
        for (int o = 16; o; o >>= 1) {
            sum += __shfl_xor_sync(0xffffffffu, sum, o);
            cnt += __shfl_xor_sync(0xffffffffu, cnt, o);
        }
        if (lane == 0) { sRN[wid] = sum; ((int*)sRD)[wid] = cnt; }
        __syncthreads();
        if (tid == 0) {
            float s = 0.0f; int c = 0;
            #pragma unroll
            for (int i = 0; i < 8; i++) { s += sRN[i]; c += ((int*)sRD)[i]; }
            out[0] = (c > 0) ? fabsf(s / (float)c) : 0.0f;
        }
    }
}

extern "C" void kernel_launch(void* const* d_in, const int* in_sizes, int n_in,
                              void* d_out, int out_size) {
    const float* emb = (const float*)d_in[0];
    const int* lab32 = (const int*)d_in[1];
    float* out = (float*)d_out;

    cudaFuncSetAttribute(sim_loss_mma, cudaFuncAttributeMaxDynamicSharedMemorySize, SMEM_BYTES);

    normalize_kernel<<<NROWS, 128>>>(emb, lab32);
    sim_loss_mma<<<GRID, 256, SMEM_BYTES>>>(out);
}

// round 12
// speedup vs baseline: 1.0405x; 1.0405x over previous
#include <cuda_runtime.h>
#include <cuda_bf16.h>
#include <cstdint>

#define NROWS 8192
#define DIM   512
#define TM    128
#define TN    128
#define KC    64              // K chunk (bf16 elems): 128 B per row
#define NC    (DIM / KC)      // 8 chunks
#define NBLK  (NROWS / TM)    // 64
#define NTILES (NBLK * (NBLK + 1) / 2)   // 2080
#define STAGES 3
#define TILE_BYTES (128 * 128)           // 16384 per operand (swizzled, no pad)
#define STAGE_BYTES (2 * TILE_BYTES)     // 32768 (A then B)
#define GRID 296              // 148 SMs x 2 CTAs -> all co-resident

#define INVT_LOG2E 20.609929155556620f   // log2(e)/0.07
#define LN2 0.69314718055994531f

// ---- scratch (__device__ globals; allocation-free rule) ----
__device__ __nv_bfloat16 g_ebf[NROWS * DIM];
__device__ float g_num[NROWS];
__device__ float g_den[NROWS];
__device__ int   g_lab[NROWS];
__device__ unsigned g_sync;   // phase-0 device barrier (reset by last CTA)
__device__ unsigned g_done;   // completion counter (reset by last CTA)

// ---- dynamic smem layout ----
#define OFF_RN (STAGES * STAGE_BYTES)          // 98304
#define OFF_RD (OFF_RN + 512)
#define OFF_CN (OFF_RD + 512)
#define OFF_CD (OFF_CN + 512)
#define SMEM_BYTES (OFF_CD + 512)              // 100352 -> 2 CTAs/SM

// swizzled smem address: row-major 128B rows, 16B seg s XOR'd with row&7
#define SWADDR(base, r, s) ((base) + ((r) << 7) + ((((s) ^ ((r) & 7))) << 4))

// ============================ PTX helpers ============================
__device__ __forceinline__ uint32_t smem_u32(const void* p) {
    uint32_t a;
    asm("{ .reg .u64 t; cvta.to.shared.u64 t, %1; cvt.u32.u64 %0, t; }" : "=r"(a) : "l"(p));
    return a;
}
#define CPA(dst, src)  asm volatile("cp.async.cg.shared.global [%0], [%1], 16;" :: "r"(dst), "l"(src))
#define CPA_COMMIT()   asm volatile("cp.async.commit_group;" ::: "memory")
#define CPA_WAIT(n)    asm volatile("cp.async.wait_group %0;" :: "n"(n) : "memory")

__device__ __forceinline__ void ldmx4(uint32_t& r0, uint32_t& r1, uint32_t& r2, uint32_t& r3,
                                      uint32_t addr) {
    asm volatile("ldmatrix.sync.aligned.m8n8.x4.shared.b16 {%0,%1,%2,%3}, [%4];"
                 : "=r"(r0), "=r"(r1), "=r"(r2), "=r"(r3) : "r"(addr));
}
__device__ __forceinline__ void mma16816(float* d, const uint32_t* a, const uint32_t* b) {
    asm volatile(
        "mma.sync.aligned.m16n8k16.row.col.f32.bf16.bf16.f32 "
        "{%0,%1,%2,%3}, {%4,%5,%6,%7}, {%8,%9}, {%0,%1,%2,%3};"
        : "+f"(d[0]), "+f"(d[1]), "+f"(d[2]), "+f"(d[3])
        : "r"(a[0]), "r"(a[1]), "r"(a[2]), "r"(a[3]), "r"(b[0]), "r"(b[1]));
}
__device__ __forceinline__ float fast_exp2(float x) {
    float y;
    asm("ex2.approx.f32 %0, %1;" : "=f"(y) : "f"(x));
    return y;
}
__device__ __forceinline__ float fast_log(float x) {
    float y;
    asm("lg2.approx.f32 %0, %1;" : "=f"(y) : "f"(x));
    return y * LN2;
}

// cp.async one 64-wide K chunk (128B/row, swizzled) of A and B into a stage buffer
__device__ __forceinline__ void load_chunk(uint32_t s, const __nv_bfloat16* A,
                                           const __nv_bfloat16* B, int k0, int tid) {
    const uint32_t sa = s, sb = s + TILE_BYTES;
    #pragma unroll
    for (int i = 0; i < 4; i++) {
        const int idx = tid + i * 256;        // 0..1023
        const int r = idx >> 3, q = idx & 7;  // row 0..127, 16B seg 0..7
        CPA(SWADDR(sa, r, q), A + (size_t)r * DIM + k0 + q * 8);
        CPA(SWADDR(sb, r, q), B + (size_t)r * DIM + k0 + q * 8);
    }
}

__device__ __forceinline__ void tile_coords(int t, int& bi, int& bj) {
    int b = 0;
    while (t >= NBLK - b) { t -= NBLK - b; b++; }
    bi = b; bj = b + t;
}

// ============================ Fused persistent kernel ============================
__global__ __launch_bounds__(256, 2)
void sim_loss_mma(const float* __restrict__ emb, const int* __restrict__ lab32,
                  float* __restrict__ out) {
    extern __shared__ __align__(128) char SM[];
    const uint32_t sbase = smem_u32(SM);
    const int tid = threadIdx.x, wid = tid >> 5, lane = tid & 31;
    const int wm = wid >> 2, wn = wid & 3;   // warp grid 2 (M) x 4 (N)

    float* sRN = (float*)(SM + OFF_RN);
    float* sRD = (float*)(SM + OFF_RD);
    float* sCN = (float*)(SM + OFF_CN);
    float* sCD = (float*)(SM + OFF_CD);

    // ======== phase 0: normalize rows -> bf16, decode labels, zero accumulators ========
    {
        __shared__ int is64_s;
        if (tid < 32) {
            // 32 odd-word probes, in-bounds under either labels layout.
            // int64 layout => all zero; int32 => P(all zero) = 512^-32 ~ 0.
            const unsigned probe = __ballot_sync(0xffffffffu, lab32[2 * tid + 1] != 0);
            if (tid == 0) is64_s = (probe == 0u) ? 1 : 0;
        }
        __syncthreads();
        const bool is64 = (is64_s != 0);

        // one row per warp, strided over all CTAs (2368 warps, 8192 rows)
        for (int r = blockIdx.x * 8 + wid; r < NROWS; r += GRID * 8) {
            const float4* in = (const float4*)(emb + (size_t)r * DIM);
            float4 x[4];
            float ss = 0.0f;
            #pragma unroll
            for (int i = 0; i < 4; i++) {
                x[i] = in[lane + 32 * i];
                ss += x[i].x * x[i].x + x[i].y * x[i].y + x[i].z * x[i].z + x[i].w * x[i].w;
            }
            #pragma unroll
            for (int o = 16; o; o >>= 1) ss += __shfl_xor_sync(0xffffffffu, ss, o);
            const float inv = rsqrtf(ss);
            uint2* outp = (uint2*)(g_ebf + (size_t)r * DIM);
            #pragma unroll
            for (int i = 0; i < 4; i++) {
                __nv_bfloat162 p0 = __floats2bfloat162_rn(x[i].x * inv, x[i].y * inv);
                __nv_bfloat162 p1 = __floats2bfloat162_rn(x[i].z * inv, x[i].w * inv);
                uint2 v;
                v.x = *(uint32_t*)&p0; v.y = *(uint32_t*)&p1;
                outp[lane + 32 * i] = v;
            }
            if (lane == 0) {
                g_num[r] = 0.0f;
                g_den[r] = 0.0f;
                g_lab[r] = is64 ? lab32[2 * r] : lab32[r];
            }
        }

        // ---- device-wide barrier (all 296 CTAs co-resident) ----
        __threadfence();
        __syncthreads();
        if (tid == 0) {
            atomicAdd(&g_sync, 1u);
            while (*(volatile unsigned*)&g_sync < (unsigned)GRID) __nanosleep(64);
        }
        __syncthreads();
        __threadfence();
    }

    // ======== phase 1: persistent GEMM + fused epilogue (round-9 structure) ========
    int t = blockIdx.x;
    int bi, bj;
    tile_coords(t, bi, bj);
    const __nv_bfloat16* Ag = g_ebf + (size_t)bi * TM * DIM;
    const __nv_bfloat16* Bg = g_ebf + (size_t)bj * TN * DIM;

    // prologue: chunks 0,1 of first tile into buffers 0,1
    load_chunk(sbase + 0 * STAGE_BYTES, Ag, Bg, 0, tid); CPA_COMMIT();
    load_chunk(sbase + 1 * STAGE_BYTES, Ag, Bg, KC, tid); CPA_COMMIT();
    int wbuf = 2;   // next buffer to write (cycles 0..2 across tiles)
    int rbuf = 0;   // buffer of current compute chunk

    float acc[4][4][4];
    #pragma unroll
    for (int i = 0; i < 4; i++)
        #pragma unroll
        for (int j = 0; j < 4; j++)
            #pragma unroll
            for (int v = 0; v < 4; v++) acc[i][j][v] = 0.0f;

    while (true) {
        const int rowBase = bi * TM, colBase = bj * TN;
        const bool offDiag = (bi != bj);

        const int tn = t + GRID;
        const bool hasNext = (tn < NTILES);
        const __nv_bfloat16 *An = Ag, *Bn = Bg;
        int nbi = bi, nbj = bj;
        if (hasNext) {
            tile_coords(tn, nbi, nbj);
            An = g_ebf + (size_t)nbi * TM * DIM;
            Bn = g_ebf + (size_t)nbj * TN * DIM;
        }

        // ---- mainloop: 8 chunks of K=64, 3-stage cycle, prefetch distance 2 ----
        #pragma unroll 1
        for (int c = 0; c < NC; c++) {
            if (c == NC - 1 && !hasNext) { CPA_WAIT(0); } else { CPA_WAIT(1); }
            __syncthreads();

            // prefetch chunk c+2 into the buffer consumed at iteration c-1
            const int pc = c + STAGES - 1;   // c + 2
            if (pc < NC) {
                load_chunk(sbase + wbuf * STAGE_BYTES, Ag, Bg, pc * KC, tid);
                CPA_COMMIT();
                wbuf = (wbuf + 1 == STAGES) ? 0 : wbuf + 1;
            } else if (hasNext && pc - NC < STAGES - 1) {
                load_chunk(sbase + wbuf * STAGE_BYTES, An, Bn, (pc - NC) * KC, tid);
                CPA_COMMIT();
                wbuf = (wbuf + 1 == STAGES) ? 0 : wbuf + 1;
            }

            const uint32_t sa = sbase + rbuf * STAGE_BYTES;
            const uint32_t sb = sa + TILE_BYTES;
            rbuf = (rbuf + 1 == STAGES) ? 0 : rbuf + 1;

            #pragma unroll
            for (int ks = 0; ks < 4; ks++) {          // four k16 steps per 64-chunk
                uint32_t bfr[4][2];
                #pragma unroll
                for (int p = 0; p < 2; p++) {
                    const int nrow = wn * 32 + p * 16 + ((lane >> 4) << 3) + (lane & 7);
                    const int seg = ks * 2 + ((lane >> 3) & 1);
                    uint32_t r0, r1, r2, r3;
                    ldmx4(r0, r1, r2, r3, SWADDR(sb, nrow, seg));
                    bfr[2 * p][0] = r0; bfr[2 * p][1] = r1;
                    bfr[2 * p + 1][0] = r2; bfr[2 * p + 1][1] = r3;
                }
                #pragma unroll
                for (int mt = 0; mt < 4; mt++) {
                    const int arow = wm * 64 + mt * 16 + (lane & 15);
                    const int aseg = ks * 2 + (lane >> 4);
                    uint32_t afr[4];
                    ldmx4(afr[0], afr[1], afr[2], afr[3], SWADDR(sa, arow, aseg));
                    #pragma unroll
                    for (int nt = 0; nt < 4; nt++)
                        mma16816(acc[mt][nt], afr, bfr[nt]);
                }
            }
        }

        // ---- epilogue (next-tile chunks 0,1 already in flight) ----
        __syncthreads();
        if (tid < 128) { sRN[tid] = 0.0f; sRD[tid] = 0.0f; }
        else           { sCN[tid - 128] = 0.0f; sCD[tid - 128] = 0.0f; }
        __syncthreads();

        int liArr[8], ljArr[8];
        #pragma unroll
        for (int mt = 0; mt < 4; mt++)
            #pragma unroll
            for (int rh = 0; rh < 2; rh++)
                liArr[mt * 2 + rh] = g_lab[rowBase + wm * 64 + mt * 16 + rh * 8 + (lane >> 2)];
        #pragma unroll
        for (int nt = 0; nt < 4; nt++)
            #pragma unroll
            for (int ce = 0; ce < 2; ce++)
                ljArr[nt * 2 + ce] = g_lab[colBase + wn * 32 + nt * 8 + 2 * (lane & 3) + ce];

        // row pass: exp once; sign carries the v>0 predicate for the col pass
        #pragma unroll
        for (int mt = 0; mt < 4; mt++) {
            #pragma unroll
            for (int rh = 0; rh < 2; rh++) {
                const int rloc = wm * 64 + mt * 16 + rh * 8 + (lane >> 2);
                const int gi = rowBase + rloc;
                const int li = liArr[mt * 2 + rh];
                float rnum = 0.0f, rden = 0.0f;
                #pragma unroll
                for (int nt = 0; nt < 4; nt++) {
                    #pragma unroll
                    for (int ce = 0; ce < 2; ce++) {
                        const int cloc = wn * 32 + nt * 8 + 2 * (lane & 3) + ce;
                        const int gj = colBase + cloc;
                        const float v = acc[mt][nt][rh * 2 + ce];
                        const float e = fast_exp2(v * INVT_LOG2E);
                        const bool diag = (gi == gj);
                        const bool pos = !diag && (li == ljArr[nt * 2 + ce]) && (v > 0.0f);
                        rden += diag ? 0.0f : e;
                        rnum += pos ? e : 0.0f;
                        acc[mt][nt][rh * 2 + ce] = (v > 0.0f) ? e : -e;
                    }
                }
                rnum += __shfl_xor_sync(0xffffffffu, rnum, 1);
                rden += __shfl_xor_sync(0xffffffffu, rden, 1);
                rnum += __shfl_xor_sync(0xffffffffu, rnum, 2);
                rden += __shfl_xor_sync(0xffffffffu, rden, 2);
                if ((lane & 3) == 0) {
                    atomicAdd(&sRD[rloc], rden);
                    if (rnum != 0.0f) atomicAdd(&sRN[rloc], rnum);
                }
            }
        }
        if (offDiag) {
            #pragma unroll
            for (int nt = 0; nt < 4; nt++) {
                #pragma unroll
                for (int ce = 0; ce < 2; ce++) {
                    const int cloc = wn * 32 + nt * 8 + 2 * (lane & 3) + ce;
                    const int lj = ljArr[nt * 2 + ce];
                    float cnum = 0.0f, cden = 0.0f;
                    #pragma unroll
                    for (int mt = 0; mt < 4; mt++) {
                        #pragma unroll
                        for (int rh = 0; rh < 2; rh++) {
                            const float s = acc[mt][nt][rh * 2 + ce];
                            const float e = fabsf(s);
                            const bool pos = (liArr[mt * 2 + rh] == lj) && (s > 0.0f);
                            cden += e;
                            cnum += pos ? e : 0.0f;
                        }
                    }
                    cnum += __shfl_xor_sync(0xffffffffu, cnum, 4);
                    cden += __shfl_xor_sync(0xffffffffu, cden, 4);
                    cnum += __shfl_xor_sync(0xffffffffu, cnum, 8);
                    cden += __shfl_xor_sync(0xffffffffu, cden, 8);
                    cnum += __shfl_xor_sync(0xffffffffu, cnum, 16);
                    cden += __shfl_xor_sync(0xffffffffu, cden, 16);
                    if (lane < 4) {   // one writer per lane&3 group
                        atomicAdd(&sCD[cloc], cden);
                        if (cnum != 0.0f) atomicAdd(&sCN[cloc], cnum);
                    }
                }
            }
        }
        __syncthreads();

        if (tid < 128) {
            atomicAdd(&g_den[rowBase + tid], sRD[tid]);
            const float rn = sRN[tid];
            if (rn != 0.0f) atomicAdd(&g_num[rowBase + tid], rn);
        } else if (offDiag) {
            const int i = tid - 128;
            atomicAdd(&g_den[colBase + i], sCD[i]);
            const float cn = sCN[i];
            if (cn != 0.0f) atomicAdd(&g_num[colBase + i], cn);
        }

        #pragma unroll
        for (int i = 0; i < 4; i++)
            #pragma unroll
            for (int j = 0; j < 4; j++)
                #pragma unroll
                for (int v = 0; v < 4; v++) acc[i][j][v] = 0.0f;

        if (!hasNext) break;
        t = tn; bi = nbi; bj = nbj; Ag = An; Bg = Bn;
    }

    // ---- grid completion: last CTA computes the final loss, resets counters ----
    __syncthreads();
    __threadfence();
    __shared__ int isLast;
    if (tid == 0) isLast = (atomicAdd(&g_done, 1u) == (unsigned)(GRID - 1)) ? 1 : 0;
    __syncthreads();
    if (isLast) {
        float sum = 0.0f;
        int cnt = 0;
        for (int i = tid; i < NROWS; i += 256) {
            const float nu = g_num[i];
            const float de = g_den[i];
            if (nu > 0.0f && de > 0.0f) {
                sum += fast_log((de + 1e-8f) / nu);
                cnt++;
            }
        }
        #pragma unroll
        for (int o = 16; o; o >>= 1) {
            sum += __shfl_xor_sync(0xffffffffu, sum, o);
            cnt += __shfl_xor_sync(0xffffffffu, cnt, o);
        }
        if (lane == 0) { sRN[wid] = sum; ((int*)sRD)[wid] = cnt; }
        __syncthreads();
        if (tid == 0) {
            float s = 0.0f; int c = 0;
            #pragma unroll
            for (int i = 0; i < 8; i++) { s += sRN[i]; c += ((int*)sRD)[i]; }
            out[0] = (c > 0) ? fabsf(s / (float)c) : 0.0f;
            // reset device barrier state for the next graph replay
            g_sync = 0u;
            g_done = 0u;
        }
    }
}

extern "C" void kernel_launch(void* const* d_in, const int* in_sizes, int n_in,
                              void* d_out, int out_size) {
    const float* emb = (const float*)d_in[0];
    const int* lab32 = (const int*)d_in[1];
    float* out = (float*)d_out;

    cudaFuncSetAttribute(sim_loss_mma, cudaFuncAttributeMaxDynamicSharedMemorySize, SMEM_BYTES);

    sim_loss_mma<<<GRID, 256, SMEM_BYTES>>>(emb, lab32, out);
}

// round 13
// speedup vs baseline: 1.0423x; 1.0017x over previous
#include <cuda_runtime.h>
#include <cuda_bf16.h>
#include <cstdint>

#define NROWS 8192
#define DIM   512
#define TM    128
#define TN    128
#define KC    64              // K chunk (bf16 elems): 128 B per row
#define NC    (DIM / KC)      // 8 chunks
#define NBLK  (NROWS / TM)    // 64
#define NTILES (NBLK * (NBLK + 1) / 2)   // 2080
#define STAGES 3
#define TILE_BYTES (128 * 128)           // 16384 per operand (swizzled, no pad)
#define STAGE_BYTES (2 * TILE_BYTES)     // 32768 (A then B)
#define GRID 296              // 148 SMs x 2 CTAs -> all co-resident

#define INVT_LOG2E 20.609929155556620f   // log2(e)/0.07
#define LN2 0.69314718055994531f

// ---- scratch (__device__ globals; allocation-free rule) ----
__device__ __nv_bfloat16 g_ebf[NROWS * DIM];
__device__ float g_num[NROWS];
__device__ float g_den[NROWS];
__device__ int   g_lab[NROWS];
__device__ unsigned g_sync;   // phase-0 device barrier (reset by last CTA)
__device__ unsigned g_done;   // completion counter (reset by last CTA)

// ---- dynamic smem layout ----
#define OFF_RN (STAGES * STAGE_BYTES)          // 98304
#define OFF_RD (OFF_RN + 512)
#define OFF_CN (OFF_RD + 512)
#define OFF_CD (OFF_CN + 512)
#define SMEM_BYTES (OFF_CD + 512)              // 100352 -> 2 CTAs/SM

// swizzled smem address: row-major 128B rows, 16B seg s XOR'd with row&7
#define SWADDR(base, r, s) ((base) + ((r) << 7) + ((((s) ^ ((r) & 7))) << 4))

// ============================ PTX helpers ============================
__device__ __forceinline__ uint32_t smem_u32(const void* p) {
    uint32_t a;
    asm("{ .reg .u64 t; cvta.to.shared.u64 t, %1; cvt.u32.u64 %0, t; }" : "=r"(a) : "l"(p));
    return a;
}
#define CPA(dst, src)  asm volatile("cp.async.cg.shared.global [%0], [%1], 16;" :: "r"(dst), "l"(src))
#define CPA_COMMIT()   asm volatile("cp.async.commit_group;" ::: "memory")
#define CPA_WAIT(n)    asm volatile("cp.async.wait_group %0;" :: "n"(n) : "memory")

__device__ __forceinline__ void ldmx4(uint32_t& r0, uint32_t& r1, uint32_t& r2, uint32_t& r3,
                                      uint32_t addr) {
    asm volatile("ldmatrix.sync.aligned.m8n8.x4.shared.b16 {%0,%1,%2,%3}, [%4];"
                 : "=r"(r0), "=r"(r1), "=r"(r2), "=r"(r3) : "r"(addr));
}
__device__ __forceinline__ void mma16816(float* d, const uint32_t* a, const uint32_t* b) {
    asm volatile(
        "mma.sync.aligned.m16n8k16.row.col.f32.bf16.bf16.f32 "
        "{%0,%1,%2,%3}, {%4,%5,%6,%7}, {%8,%9}, {%0,%1,%2,%3};"
        : "+f"(d[0]), "+f"(d[1]), "+f"(d[2]), "+f"(d[3])
        : "r"(a[0]), "r"(a[1]), "r"(a[2]), "r"(a[3]), "r"(b[0]), "r"(b[1]));
}
__device__ __forceinline__ float fast_exp2(float x) {
    float y;
    asm("ex2.approx.f32 %0, %1;" : "=f"(y) : "f"(x));
    return y;
}
__device__ __forceinline__ float fast_log(float x) {
    float y;
    asm("lg2.approx.f32 %0, %1;" : "=f"(y) : "f"(x));
    return y * LN2;
}

// cp.async one 64-wide K chunk (128B/row, swizzled) of A and B into a stage buffer
__device__ __forceinline__ void load_chunk(uint32_t s, const __nv_bfloat16* A,
                                           const __nv_bfloat16* B, int k0, int tid) {
    const uint32_t sa = s, sb = s + TILE_BYTES;
    #pragma unroll
    for (int i = 0; i < 4; i++) {
        const int idx = tid + i * 256;        // 0..1023
        const int r = idx >> 3, q = idx & 7;  // row 0..127, 16B seg 0..7
        CPA(SWADDR(sa, r, q), A + (size_t)r * DIM + k0 + q * 8);
        CPA(SWADDR(sb, r, q), B + (size_t)r * DIM + k0 + q * 8);
    }
}

__device__ __forceinline__ void tile_coords(int t, int& bi, int& bj) {
    int b = 0;
    while (t >= NBLK - b) { t -= NBLK - b; b++; }
    bi = b; bj = b + t;
}

// ============================ Fused persistent kernel ============================
__global__ __launch_bounds__(256, 2)
void sim_loss_mma(const float* __restrict__ emb, const int* __restrict__ lab32,
                  float* __restrict__ out) {
    extern __shared__ __align__(128) char SM[];
    const uint32_t sbase = smem_u32(SM);
    const int tid = threadIdx.x, wid = tid >> 5, lane = tid & 31;
    const int wm = wid >> 2, wn = wid & 3;   // warp grid 2 (M) x 4 (N)

    float* sRN = (float*)(SM + OFF_RN);
    float* sRD = (float*)(SM + OFF_RD);
    float* sCN = (float*)(SM + OFF_CN);
    float* sCD = (float*)(SM + OFF_CD);

    // ======== phase 0: normalize rows -> bf16, decode labels, zero accumulators ========
    {
        __shared__ int is64_s;
        if (tid < 32) {
            // 32 odd-word probes, in-bounds under either labels layout.
            // int64 layout => all zero; int32 => P(all zero) = 512^-32 ~ 0.
            const unsigned probe = __ballot_sync(0xffffffffu, lab32[2 * tid + 1] != 0);
            if (tid == 0) is64_s = (probe == 0u) ? 1 : 0;
        }
        __syncthreads();
        const bool is64 = (is64_s != 0);

        // one row per warp, strided over all CTAs (2368 warps, 8192 rows)
        for (int r = blockIdx.x * 8 + wid; r < NROWS; r += GRID * 8) {
            const float4* in = (const float4*)(emb + (size_t)r * DIM);
            float4 x[4];
            float ss = 0.0f;
            #pragma unroll
            for (int i = 0; i < 4; i++) {
                x[i] = in[lane + 32 * i];
                ss += x[i].x * x[i].x + x[i].y * x[i].y + x[i].z * x[i].z + x[i].w * x[i].w;
            }
            #pragma unroll
            for (int o = 16; o; o >>= 1) ss += __shfl_xor_sync(0xffffffffu, ss, o);
            const float inv = rsqrtf(ss);
            uint2* outp = (uint2*)(g_ebf + (size_t)r * DIM);
            #pragma unroll
            for (int i = 0; i < 4; i++) {
                __nv_bfloat162 p0 = __floats2bfloat162_rn(x[i].x * inv, x[i].y * inv);
                __nv_bfloat162 p1 = __floats2bfloat162_rn(x[i].z * inv, x[i].w * inv);
                uint2 v;
                v.x = *(uint32_t*)&p0; v.y = *(uint32_t*)&p1;
                outp[lane + 32 * i] = v;
            }
            if (lane == 0) {
                g_num[r] = 0.0f;
                g_den[r] = 0.0f;
                g_lab[r] = is64 ? lab32[2 * r] : lab32[r];
            }
        }

        // ---- device-wide barrier (all 296 CTAs co-resident) ----
        __threadfence();
        __syncthreads();
        if (tid == 0) {
            atomicAdd(&g_sync, 1u);
            while (*(volatile unsigned*)&g_sync < (unsigned)GRID) __nanosleep(64);
        }
        __syncthreads();
        __threadfence();
    }

    // ======== phase 1: persistent GEMM + fused epilogue ========
    int t = blockIdx.x;
    int bi, bj;
    tile_coords(t, bi, bj);
    const __nv_bfloat16* Ag = g_ebf + (size_t)bi * TM * DIM;
    const __nv_bfloat16* Bg = g_ebf + (size_t)bj * TN * DIM;

    // prologue: chunks 0,1 of first tile into buffers 0,1
    load_chunk(sbase + 0 * STAGE_BYTES, Ag, Bg, 0, tid); CPA_COMMIT();
    load_chunk(sbase + 1 * STAGE_BYTES, Ag, Bg, KC, tid); CPA_COMMIT();
    int wbuf = 2;   // next buffer to write (cycles 0..2 across tiles)
    int rbuf = 0;   // buffer of current compute chunk

    float acc[4][4][4];
    #pragma unroll
    for (int i = 0; i < 4; i++)
        #pragma unroll
        for (int j = 0; j < 4; j++)
            #pragma unroll
            for (int v = 0; v < 4; v++) acc[i][j][v] = 0.0f;

    while (true) {
        const int rowBase = bi * TM, colBase = bj * TN;
        const bool offDiag = (bi != bj);

        const int tn = t + GRID;
        const bool hasNext = (tn < NTILES);
        const __nv_bfloat16 *An = Ag, *Bn = Bg;
        int nbi = bi, nbj = bj;
        if (hasNext) {
            tile_coords(tn, nbi, nbj);
            An = g_ebf + (size_t)nbi * TM * DIM;
            Bn = g_ebf + (size_t)nbj * TN * DIM;
        }

        // ---- mainloop: 8 chunks of K=64, 3-stage cycle, prefetch distance 2 ----
        #pragma unroll 1
        for (int c = 0; c < NC; c++) {
            if (c == NC - 1 && !hasNext) { CPA_WAIT(0); } else { CPA_WAIT(1); }
            __syncthreads();

            // prefetch chunk c+2 into the buffer consumed at iteration c-1
            const int pc = c + STAGES - 1;   // c + 2
            if (pc < NC) {
                load_chunk(sbase + wbuf * STAGE_BYTES, Ag, Bg, pc * KC, tid);
                CPA_COMMIT();
                wbuf = (wbuf + 1 == STAGES) ? 0 : wbuf + 1;
            } else if (hasNext && pc - NC < STAGES - 1) {
                load_chunk(sbase + wbuf * STAGE_BYTES, An, Bn, (pc - NC) * KC, tid);
                CPA_COMMIT();
                wbuf = (wbuf + 1 == STAGES) ? 0 : wbuf + 1;
            }

            const uint32_t sa = sbase + rbuf * STAGE_BYTES;
            const uint32_t sb = sa + TILE_BYTES;
            rbuf = (rbuf + 1 == STAGES) ? 0 : rbuf + 1;

            // warp-staggered ks order: desynchronize LDSM bursts across warps so
            // one warp's ldmatrix drain overlaps other warps' HMMA phases.
            #pragma unroll
            for (int kk = 0; kk < 4; kk++) {
                const int ks = (kk + wid) & 3;
                uint32_t bfr[4][2];
                #pragma unroll
                for (int p = 0; p < 2; p++) {
                    const int nrow = wn * 32 + p * 16 + ((lane >> 4) << 3) + (lane & 7);
                    const int seg = ks * 2 + ((lane >> 3) & 1);
                    uint32_t r0, r1, r2, r3;
                    ldmx4(r0, r1, r2, r3, SWADDR(sb, nrow, seg));
                    bfr[2 * p][0] = r0; bfr[2 * p][1] = r1;
                    bfr[2 * p + 1][0] = r2; bfr[2 * p + 1][1] = r3;
                }
                #pragma unroll
                for (int mt = 0; mt < 4; mt++) {
                    const int arow = wm * 64 + mt * 16 + (lane & 15);
                    const int aseg = ks * 2 + (lane >> 4);
                    uint32_t afr[4];
                    ldmx4(afr[0], afr[1], afr[2], afr[3], SWADDR(sa, arow, aseg));
                    #pragma unroll
                    for (int nt = 0; nt < 4; nt++)
                        mma16816(acc[mt][nt], afr, bfr[nt]);
                }
            }
        }

        // ---- epilogue (next-tile chunks 0,1 already in flight) ----
        __syncthreads();
        if (tid < 128) { sRN[tid] = 0.0f; sRD[tid] = 0.0f; }
        else           { sCN[tid - 128] = 0.0f; sCD[tid - 128] = 0.0f; }
        __syncthreads();

        int liArr[8], ljArr[8];
        #pragma unroll
        for (int mt = 0; mt < 4; mt++)
            #pragma unroll
            for (int rh = 0; rh < 2; rh++)
                liArr[mt * 2 + rh] = g_lab[rowBase + wm * 64 + mt * 16 + rh * 8 + (lane >> 2)];
        #pragma unroll
        for (int nt = 0; nt < 4; nt++)
            #pragma unroll
            for (int ce = 0; ce < 2; ce++)
                ljArr[nt * 2 + ce] = g_lab[colBase + wn * 32 + nt * 8 + 2 * (lane & 3) + ce];

        // row pass: exp once; sign carries the v>0 predicate for the col pass
        #pragma unroll
        for (int mt = 0; mt < 4; mt++) {
            #pragma unroll
            for (int rh = 0; rh < 2; rh++) {
                const int rloc = wm * 64 + mt * 16 + rh * 8 + (lane >> 2);
                const int gi = rowBase + rloc;
                const int li = liArr[mt * 2 + rh];
                float rnum = 0.0f, rden = 0.0f;
                #pragma unroll
                for (int nt = 0; nt < 4; nt++) {
                    #pragma unroll
                    for (int ce = 0; ce < 2; ce++) {
                        const int cloc = wn * 32 + nt * 8 + 2 * (lane & 3) + ce;
                        const int gj = colBase + cloc;
                        const float v = acc[mt][nt][rh * 2 + ce];
                        const float e = fast_exp2(v * INVT_LOG2E);
                        const bool diag = (gi == gj);
                        const bool pos = !diag && (li == ljArr[nt * 2 + ce]) && (v > 0.0f);
                        rden += diag ? 0.0f : e;
                        rnum += pos ? e : 0.0f;
                        acc[mt][nt][rh * 2 + ce] = (v > 0.0f) ? e : -e;
                    }
                }
                rnum += __shfl_xor_sync(0xffffffffu, rnum, 1);
                rden += __shfl_xor_sync(0xffffffffu, rden, 1);
                rnum += __shfl_xor_sync(0xffffffffu, rnum, 2);
                rden += __shfl_xor_sync(0xffffffffu, rden, 2);
                if ((lane & 3) == 0) {
                    atomicAdd(&sRD[rloc], rden);
                    if (rnum != 0.0f) atomicAdd(&sRN[rloc], rnum);
                }
            }
        }
        if (offDiag) {
            #pragma unroll
            for (int nt = 0; nt < 4; nt++) {
                #pragma unroll
                for (int ce = 0; ce < 2; ce++) {
                    const int cloc = wn * 32 + nt * 8 + 2 * (lane & 3) + ce;
                    const int lj = ljArr[nt * 2 + ce];
                    float cnum = 0.0f, cden = 0.0f;
                    #pragma unroll
                    for (int mt = 0; mt < 4; mt++) {
                        #pragma unroll
                        for (int rh = 0; rh < 2; rh++) {
                            const float s = acc[mt][nt][rh * 2 + ce];
                            const float e = fabsf(s);
                            const bool pos = (liArr[mt * 2 + rh] == lj) && (s > 0.0f);
                            cden += e;
                            cnum += pos ? e : 0.0f;
                        }
                    }
                    cnum += __shfl_xor_sync(0xffffffffu, cnum, 4);
                    cden += __shfl_xor_sync(0xffffffffu, cden, 4);
                    cnum += __shfl_xor_sync(0xffffffffu, cnum, 8);
                    cden += __shfl_xor_sync(0xffffffffu, cden, 8);
                    cnum += __shfl_xor_sync(0xffffffffu, cnum, 16);
                    cden += __shfl_xor_sync(0xffffffffu, cden, 16);
                    if (lane < 4) {   // one writer per lane&3 group
                        atomicAdd(&sCD[cloc], cden);
                        if (cnum != 0.0f) atomicAdd(&sCN[cloc], cnum);
                    }
                }
            }
        }
        __syncthreads();

        if (tid < 128) {
            atomicAdd(&g_den[rowBase + tid], sRD[tid]);
            const float rn = sRN[tid];
            if (rn != 0.0f) atomicAdd(&g_num[rowBase + tid], rn);
        } else if (offDiag) {
            const int i = tid - 128;
            atomicAdd(&g_den[colBase + i], sCD[i]);
            const float cn = sCN[i];
            if (cn != 0.0f) atomicAdd(&g_num[colBase + i], cn);
        }

        #pragma unroll
        for (int i = 0; i < 4; i++)
            #pragma unroll
            for (int j = 0; j < 4; j++)
                #pragma unroll
                for (int v = 0; v < 4; v++) acc[i][j][v] = 0.0f;

        if (!hasNext) break;
        t = tn; bi = nbi; bj = nbj; Ag = An; Bg = Bn;
    }

    // ---- grid completion: last CTA computes the final loss, resets counters ----
    __syncthreads();
    __threadfence();
    __shared__ int isLast;
    if (tid == 0) isLast = (atomicAdd(&g_done, 1u) == (unsigned)(GRID - 1)) ? 1 : 0;
    __syncthreads();
    if (isLast) {
        float sum = 0.0f;
        int cnt = 0;
        for (int i = tid; i < NROWS; i += 256) {
            const float nu = g_num[i];
            const float de = g_den[i];
            if (nu > 0.0f && de > 0.0f) {
                sum += fast_log((de + 1e-8f) / nu);
                cnt++;
            }
        }
        #pragma unroll
        for (int o = 16; o; o >>= 1) {
            sum += __shfl_xor_sync(0xffffffffu, sum, o);
            cnt += __shfl_xor_sync(0xffffffffu, cnt, o);
        }
        if (lane == 0) { sRN[wid] = sum; ((int*)sRD)[wid] = cnt; }
        __syncthreads();
        if (tid == 0) {
            float s = 0.0f; int c = 0;
            #pragma unroll
            for (int i = 0; i < 8; i++) { s += sRN[i]; c += ((int*)sRD)[i]; }
            out[0] = (c > 0) ? fabsf(s / (float)c) : 0.0f;
            // reset device barrier state for the next graph replay
            g_sync = 0u;
            g_done = 0u;
        }
    }
}

extern "C" void kernel_launch(void* const* d_in, const int* in_sizes, int n_in,
                              void* d_out, int out_size) {
    const float* emb = (const float*)d_in[0];
    const int* lab32 = (const int*)d_in[1];
    float* out = (float*)d_out;

    cudaFuncSetAttribute(sim_loss_mma, cudaFuncAttributeMaxDynamicSharedMemorySize, SMEM_BYTES);

    sim_loss_mma<<<GRID, 256, SMEM_BYTES>>>(emb, lab32, out);
}

// round 14
// speedup vs baseline: 1.0880x; 1.0439x over previous
#include <cuda_runtime.h>
#include <cuda_bf16.h>
#include <cstdint>

#define NROWS 8192
#define DIM   512
#define TM    128
#define TN    128
#define KC    64              // K chunk (bf16 elems): 128 B per row
#define NC    (DIM / KC)      // 8 chunks
#define NBLK  (NROWS / TM)    // 64
#define NTILES (NBLK * (NBLK + 1) / 2)   // 2080
#define STAGES 3
#define TILE_BYTES (128 * 128)           // 16384 per operand (swizzled, no pad)
#define STAGE_BYTES (2 * TILE_BYTES)     // 32768 (A then B)
#define GRID 296              // 148 SMs x 2 CTAs -> all co-resident

#define INVT_LOG2E 20.609929155556620f   // log2(e)/0.07
#define LN2 0.69314718055994531f

// ---- scratch (__device__ globals; allocation-free rule) ----
__device__ __nv_bfloat16 g_ebf[NROWS * DIM];
__device__ float g_num[NROWS];
__device__ float g_den[NROWS];
__device__ int   g_lab[NROWS];
__device__ unsigned g_sync;   // phase-0 device barrier (reset by last CTA)
__device__ unsigned g_done;   // completion counter (reset by last CTA)

// ---- dynamic smem layout ----
#define OFF_RN (STAGES * STAGE_BYTES)          // 98304
#define OFF_RD (OFF_RN + 512)
#define OFF_CN (OFF_RD + 512)
#define OFF_CD (OFF_CN + 512)
#define SMEM_BYTES (OFF_CD + 512)              // 100352 -> 2 CTAs/SM

// swizzled smem address: row-major 128B rows, 16B seg s XOR'd with row&7
#define SWADDR(base, r, s) ((base) + ((r) << 7) + ((((s) ^ ((r) & 7))) << 4))

// ============================ PTX helpers ============================
__device__ __forceinline__ uint32_t smem_u32(const void* p) {
    uint32_t a;
    asm("{ .reg .u64 t; cvta.to.shared.u64 t, %1; cvt.u32.u64 %0, t; }" : "=r"(a) : "l"(p));
    return a;
}
#define CPA(dst, src)  asm volatile("cp.async.cg.shared.global [%0], [%1], 16;" :: "r"(dst), "l"(src))
#define CPA_COMMIT()   asm volatile("cp.async.commit_group;" ::: "memory")
#define CPA_WAIT(n)    asm volatile("cp.async.wait_group %0;" :: "n"(n) : "memory")

__device__ __forceinline__ void ldmx4(uint32_t& r0, uint32_t& r1, uint32_t& r2, uint32_t& r3,
                                      uint32_t addr) {
    asm volatile("ldmatrix.sync.aligned.m8n8.x4.shared.b16 {%0,%1,%2,%3}, [%4];"
                 : "=r"(r0), "=r"(r1), "=r"(r2), "=r"(r3) : "r"(addr));
}
__device__ __forceinline__ void mma16816(float* d, const uint32_t* a, const uint32_t* b) {
    asm volatile(
        "mma.sync.aligned.m16n8k16.row.col.f32.bf16.bf16.f32 "
        "{%0,%1,%2,%3}, {%4,%5,%6,%7}, {%8,%9}, {%0,%1,%2,%3};"
        : "+f"(d[0]), "+f"(d[1]), "+f"(d[2]), "+f"(d[3])
        : "r"(a[0]), "r"(a[1]), "r"(a[2]), "r"(a[3]), "r"(b[0]), "r"(b[1]));
}
__device__ __forceinline__ float fast_exp2(float x) {
    float y;
    asm("ex2.approx.f32 %0, %1;" : "=f"(y) : "f"(x));
    return y;
}
__device__ __forceinline__ float fast_log(float x) {
    float y;
    asm("lg2.approx.f32 %0, %1;" : "=f"(y) : "f"(x));
    return y * LN2;
}

// cp.async one 64-wide K chunk (128B/row, swizzled) of A and B into a stage buffer
__device__ __forceinline__ void load_chunk(uint32_t s, const __nv_bfloat16* A,
                                           const __nv_bfloat16* B, int k0, int tid) {
    const uint32_t sa = s, sb = s + TILE_BYTES;
    #pragma unroll
    for (int i = 0; i < 4; i++) {
        const int idx = tid + i * 256;        // 0..1023
        const int r = idx >> 3, q = idx & 7;  // row 0..127, 16B seg 0..7
        CPA(SWADDR(sa, r, q), A + (size_t)r * DIM + k0 + q * 8);
        CPA(SWADDR(sb, r, q), B + (size_t)r * DIM + k0 + q * 8);
    }
}

__device__ __forceinline__ void tile_coords(int t, int& bi, int& bj) {
    int b = 0;
    while (t >= NBLK - b) { t -= NBLK - b; b++; }
    bi = b; bj = b + t;
}

// ============================ Fused persistent kernel ============================
__global__ __launch_bounds__(256, 2)
void sim_loss_mma(const float* __restrict__ emb, const int* __restrict__ lab32,
                  float* __restrict__ out) {
    extern __shared__ __align__(128) char SM[];
    const uint32_t sbase = smem_u32(SM);
    const int tid = threadIdx.x, wid = tid >> 5, lane = tid & 31;
    const int wm = wid >> 2, wn = wid & 3;   // warp grid 2 (M) x 4 (N)

    float* sRN = (float*)(SM + OFF_RN);
    float* sRD = (float*)(SM + OFF_RD);
    float* sCN = (float*)(SM + OFF_CN);
    float* sCD = (float*)(SM + OFF_CD);

    // ======== phase 0: normalize rows -> bf16, decode labels, zero accumulators ========
    {
        __shared__ int is64_s;
        if (tid < 32) {
            // 32 odd-word probes, in-bounds under either labels layout.
            // int64 layout => all zero; int32 => P(all zero) = 512^-32 ~ 0.
            const unsigned probe = __ballot_sync(0xffffffffu, lab32[2 * tid + 1] != 0);
            if (tid == 0) is64_s = (probe == 0u) ? 1 : 0;
        }
        __syncthreads();
        const bool is64 = (is64_s != 0);

        // one row per warp, strided over all CTAs (2368 warps, 8192 rows)
        for (int r = blockIdx.x * 8 + wid; r < NROWS; r += GRID * 8) {
            const float4* in = (const float4*)(emb + (size_t)r * DIM);
            float4 x[4];
            float ss = 0.0f;
            #pragma unroll
            for (int i = 0; i < 4; i++) {
                x[i] = in[lane + 32 * i];
                ss += x[i].x * x[i].x + x[i].y * x[i].y + x[i].z * x[i].z + x[i].w * x[i].w;
            }
            #pragma unroll
            for (int o = 16; o; o >>= 1) ss += __shfl_xor_sync(0xffffffffu, ss, o);
            const float inv = rsqrtf(ss);
            uint2* outp = (uint2*)(g_ebf + (size_t)r * DIM);
            #pragma unroll
            for (int i = 0; i < 4; i++) {
                __nv_bfloat162 p0 = __floats2bfloat162_rn(x[i].x * inv, x[i].y * inv);
                __nv_bfloat162 p1 = __floats2bfloat162_rn(x[i].z * inv, x[i].w * inv);
                uint2 v;
                v.x = *(uint32_t*)&p0; v.y = *(uint32_t*)&p1;
                outp[lane + 32 * i] = v;
            }
            if (lane == 0) {
                g_num[r] = 0.0f;
                g_den[r] = 0.0f;
                g_lab[r] = is64 ? lab32[2 * r] : lab32[r];
            }
        }

        // ---- device-wide barrier (all 296 CTAs co-resident) ----
        __threadfence();
        __syncthreads();
        if (tid == 0) {
            atomicAdd(&g_sync, 1u);
            while (*(volatile unsigned*)&g_sync < (unsigned)GRID) __nanosleep(64);
        }
        __syncthreads();
        __threadfence();
    }

    // ======== phase 1: persistent GEMM + fused epilogue ========
    int t = blockIdx.x;
    int bi, bj;
    tile_coords(t, bi, bj);
    const __nv_bfloat16* Ag = g_ebf + (size_t)bi * TM * DIM;
    const __nv_bfloat16* Bg = g_ebf + (size_t)bj * TN * DIM;

    // prologue: chunks 0,1 of first tile into buffers 0,1
    load_chunk(sbase + 0 * STAGE_BYTES, Ag, Bg, 0, tid); CPA_COMMIT();
    load_chunk(sbase + 1 * STAGE_BYTES, Ag, Bg, KC, tid); CPA_COMMIT();
    int wbuf = 2;   // next buffer to write (cycles 0..2 across tiles)
    int rbuf = 0;   // buffer of current compute chunk

    float acc[4][4][4];
    #pragma unroll
    for (int i = 0; i < 4; i++)
        #pragma unroll
        for (int j = 0; j < 4; j++)
            #pragma unroll
            for (int v = 0; v < 4; v++) acc[i][j][v] = 0.0f;

    while (true) {
        const int rowBase = bi * TM, colBase = bj * TN;
        const bool offDiag = (bi != bj);

        const int tn = t + GRID;
        const bool hasNext = (tn < NTILES);
        const __nv_bfloat16 *An = Ag, *Bn = Bg;
        int nbi = bi, nbj = bj;
        if (hasNext) {
            tile_coords(tn, nbi, nbj);
            An = g_ebf + (size_t)nbi * TM * DIM;
            Bn = g_ebf + (size_t)nbj * TN * DIM;
        }

        // ---- mainloop: 8 chunks of K=64, 3-stage cycle, prefetch distance 2 ----
        #pragma unroll 1
        for (int c = 0; c < NC; c++) {
            if (c == NC - 1 && !hasNext) { CPA_WAIT(0); } else { CPA_WAIT(1); }
            __syncthreads();

            // prefetch chunk c+2 into the buffer consumed at iteration c-1
            const int pc = c + STAGES - 1;   // c + 2
            if (pc < NC) {
                load_chunk(sbase + wbuf * STAGE_BYTES, Ag, Bg, pc * KC, tid);
                CPA_COMMIT();
                wbuf = (wbuf + 1 == STAGES) ? 0 : wbuf + 1;
            } else if (hasNext && pc - NC < STAGES - 1) {
                load_chunk(sbase + wbuf * STAGE_BYTES, An, Bn, (pc - NC) * KC, tid);
                CPA_COMMIT();
                wbuf = (wbuf + 1 == STAGES) ? 0 : wbuf + 1;
            }

            const uint32_t sa = sbase + rbuf * STAGE_BYTES;
            const uint32_t sb = sa + TILE_BYTES;
            rbuf = (rbuf + 1 == STAGES) ? 0 : rbuf + 1;

            #pragma unroll
            for (int ks = 0; ks < 4; ks++) {          // four k16 steps per 64-chunk
                uint32_t bfr[4][2];
                #pragma unroll
                for (int p = 0; p < 2; p++) {
                    const int nrow = wn * 32 + p * 16 + ((lane >> 4) << 3) + (lane & 7);
                    const int seg = ks * 2 + ((lane >> 3) & 1);
                    uint32_t r0, r1, r2, r3;
                    ldmx4(r0, r1, r2, r3, SWADDR(sb, nrow, seg));
                    bfr[2 * p][0] = r0; bfr[2 * p][1] = r1;
                    bfr[2 * p + 1][0] = r2; bfr[2 * p + 1][1] = r3;
                }
                #pragma unroll
                for (int mt = 0; mt < 4; mt++) {
                    const int arow = wm * 64 + mt * 16 + (lane & 15);
                    const int aseg = ks * 2 + (lane >> 4);
                    uint32_t afr[4];
                    ldmx4(afr[0], afr[1], afr[2], afr[3], SWADDR(sa, arow, aseg));
                    #pragma unroll
                    for (int nt = 0; nt < 4; nt++)
                        mma16816(acc[mt][nt], afr, bfr[nt]);
                }
            }
        }

        // ---- single-pass fused epilogue (next-tile chunks 0,1 already in flight) ----
        __syncthreads();
        if (tid < 128) { sRN[tid] = 0.0f; sRD[tid] = 0.0f; }
        else           { sCN[tid - 128] = 0.0f; sCD[tid - 128] = 0.0f; }
        __syncthreads();

        int liArr[8], ljArr[8];
        #pragma unroll
        for (int mt = 0; mt < 4; mt++)
            #pragma unroll
            for (int rh = 0; rh < 2; rh++)
                liArr[mt * 2 + rh] = g_lab[rowBase + wm * 64 + mt * 16 + rh * 8 + (lane >> 2)];
        #pragma unroll
        for (int nt = 0; nt < 4; nt++)
            #pragma unroll
            for (int ce = 0; ce < 2; ce++)
                ljArr[nt * 2 + ce] = g_lab[colBase + wn * 32 + nt * 8 + 2 * (lane & 3) + ce];

        // one pass over all 64 elements: exp once, row AND col accumulation together
        float cnum[8], cden[8];
        #pragma unroll
        for (int i = 0; i < 8; i++) { cnum[i] = 0.0f; cden[i] = 0.0f; }

        #pragma unroll
        for (int mt = 0; mt < 4; mt++) {
            #pragma unroll
            for (int rh = 0; rh < 2; rh++) {
                const int rloc = wm * 64 + mt * 16 + rh * 8 + (lane >> 2);
                const int gi = rowBase + rloc;
                const int li = liArr[mt * 2 + rh];
                float rnum = 0.0f, rden = 0.0f;
                #pragma unroll
                for (int nt = 0; nt < 4; nt++) {
                    #pragma unroll
                    for (int ce = 0; ce < 2; ce++) {
                        const int j = nt * 2 + ce;
                        const int cloc = wn * 32 + nt * 8 + 2 * (lane & 3) + ce;
                        const float v = acc[mt][nt][rh * 2 + ce];
                        const float e = fast_exp2(v * INVT_LOG2E);
                        const bool diag = (gi == colBase + cloc);
                        const bool pos = !diag && (li == ljArr[j]) && (v > 0.0f);
                        const float de = diag ? 0.0f : e;
                        const float nu = pos ? e : 0.0f;
                        rden += de; rnum += nu;
                        cden[j] += de; cnum[j] += nu;   // only used on offDiag tiles
                    }
                }
                rnum += __shfl_xor_sync(0xffffffffu, rnum, 1);
                rden += __shfl_xor_sync(0xffffffffu, rden, 1);
                rnum += __shfl_xor_sync(0xffffffffu, rnum, 2);
                rden += __shfl_xor_sync(0xffffffffu, rden, 2);
                if ((lane & 3) == 0) {
                    atomicAdd(&sRD[rloc], rden);
                    if (rnum != 0.0f) atomicAdd(&sRN[rloc], rnum);
                }
            }
        }
        if (offDiag) {
            #pragma unroll
            for (int nt = 0; nt < 4; nt++) {
                #pragma unroll
                for (int ce = 0; ce < 2; ce++) {
                    const int j = nt * 2 + ce;
                    const int cloc = wn * 32 + nt * 8 + 2 * (lane & 3) + ce;
                    float cn = cnum[j], cd = cden[j];
                    cn += __shfl_xor_sync(0xffffffffu, cn, 4);
                    cd += __shfl_xor_sync(0xffffffffu, cd, 4);
                    cn += __shfl_xor_sync(0xffffffffu, cn, 8);
                    cd += __shfl_xor_sync(0xffffffffu, cd, 8);
                    cn += __shfl_xor_sync(0xffffffffu, cn, 16);
                    cd += __shfl_xor_sync(0xffffffffu, cd, 16);
                    if (lane < 4) {   // one writer per lane&3 group
                        atomicAdd(&sCD[cloc], cd);
                        if (cn != 0.0f) atomicAdd(&sCN[cloc], cn);
                    }
                }
            }
        }
        __syncthreads();

        if (tid < 128) {
            atomicAdd(&g_den[rowBase + tid], sRD[tid]);
            const float rn = sRN[tid];
            if (rn != 0.0f) atomicAdd(&g_num[rowBase + tid], rn);
        } else if (offDiag) {
            const int i = tid - 128;
            atomicAdd(&g_den[colBase + i], sCD[i]);
            const float cn = sCN[i];
            if (cn != 0.0f) atomicAdd(&g_num[colBase + i], cn);
        }

        #pragma unroll
        for (int i = 0; i < 4; i++)
            #pragma unroll
            for (int j = 0; j < 4; j++)
                #pragma unroll
                for (int v = 0; v < 4; v++) acc[i][j][v] = 0.0f;

        if (!hasNext) break;
        t = tn; bi = nbi; bj = nbj; Ag = An; Bg = Bn;
    }

    // ---- grid completion: last CTA computes the final loss, resets counters ----
    __syncthreads();
    __threadfence();
    __shared__ int isLast;
    if (tid == 0) isLast = (atomicAdd(&g_done, 1u) == (unsigned)(GRID - 1)) ? 1 : 0;
    __syncthreads();
    if (isLast) {
        float sum = 0.0f;
        int cnt = 0;
        for (int i = tid; i < NROWS; i += 256) {
            const float nu = g_num[i];
            const float de = g_den[i];
            if (nu > 0.0f && de > 0.0f) {
                sum += fast_log((de + 1e-8f) / nu);
                cnt++;
            }
        }
        #pragma unroll
        for (int o = 16; o; o >>= 1) {
            sum += __shfl_xor_sync(0xffffffffu, sum, o);
            cnt += __shfl_xor_sync(0xffffffffu, cnt, o);
        }
        if (lane == 0) { sRN[wid] = sum; ((int*)sRD)[wid] = cnt; }
        __syncthreads();
        if (tid == 0) {
            float s = 0.0f; int c = 0;
            #pragma unroll
            for (int i = 0; i < 8; i++) { s += sRN[i]; c += ((int*)sRD)[i]; }
            out[0] = (c > 0) ? fabsf(s / (float)c) : 0.0f;
            // reset device barrier state for the next graph replay
            g_sync = 0u;
            g_done = 0u;
        }
    }
}

extern "C" void kernel_launch(void* const* d_in, const int* in_sizes, int n_in,
                              void* d_out, int out_size) {
    const float* emb = (const float*)d_in[0];
    const int* lab32 = (const int*)d_in[1];
    float* out = (float*)d_out;

    cudaFuncSetAttribute(sim_loss_mma, cudaFuncAttributeMaxDynamicSharedMemorySize, SMEM_BYTES);

    sim_loss_mma<<<GRID, 256, SMEM_BYTES>>>(emb, lab32, out);
}

// round 15
// speedup vs baseline: 1.1055x; 1.0161x over previous
#include <cuda_runtime.h>
#include <cuda_bf16.h>
#include <cstdint>

#define NROWS 8192
#define DIM   512
#define TM    128
#define TN    128
#define KC    64              // K chunk (bf16 elems): 128 B per row
#define NC    (DIM / KC)      // 8 chunks
#define NBLK  (NROWS / TM)    // 64
#define NTILES (NBLK * (NBLK + 1) / 2)   // 2080
#define STAGES 3
#define TILE_BYTES (128 * 128)           // 16384 per operand (swizzled, no pad)
#define STAGE_BYTES (2 * TILE_BYTES)     // 32768 (A then B)
#define GRID 296              // 148 SMs x 2 CTAs -> all co-resident

#define INVT_LOG2E 20.609929155556620f   // log2(e)/0.07
#define LN2 0.69314718055994531f

// ---- scratch (__device__ globals; allocation-free rule) ----
__device__ __nv_bfloat16 g_ebf[NROWS * DIM];
__device__ float g_num[NROWS];
__device__ float g_den[NROWS];
__device__ int   g_lab[NROWS];
__device__ unsigned g_sync;   // phase-0 device barrier (reset by last CTA)
__device__ unsigned g_done;   // completion counter (reset by last CTA)

// ---- dynamic smem layout ----
#define OFF_RN (STAGES * STAGE_BYTES)          // 98304
#define OFF_RD (OFF_RN + 512)
#define OFF_CN (OFF_RD + 512)
#define OFF_CD (OFF_CN + 512)
#define SMEM_BYTES (OFF_CD + 512)              // 100352 -> 2 CTAs/SM

// swizzled smem address: row-major 128B rows, 16B seg s XOR'd with row&7
#define SWADDR(base, r, s) ((base) + ((r) << 7) + ((((s) ^ ((r) & 7))) << 4))

// ============================ PTX helpers ============================
__device__ __forceinline__ uint32_t smem_u32(const void* p) {
    uint32_t a;
    asm("{ .reg .u64 t; cvta.to.shared.u64 t, %1; cvt.u32.u64 %0, t; }" : "=r"(a) : "l"(p));
    return a;
}
#define CPA(dst, src)  asm volatile("cp.async.cg.shared.global [%0], [%1], 16;" :: "r"(dst), "l"(src))
#define CPA_COMMIT()   asm volatile("cp.async.commit_group;" ::: "memory")
#define CPA_WAIT(n)    asm volatile("cp.async.wait_group %0;" :: "n"(n) : "memory")

__device__ __forceinline__ void ldmx4(uint32_t& r0, uint32_t& r1, uint32_t& r2, uint32_t& r3,
                                      uint32_t addr) {
    asm volatile("ldmatrix.sync.aligned.m8n8.x4.shared.b16 {%0,%1,%2,%3}, [%4];"
                 : "=r"(r0), "=r"(r1), "=r"(r2), "=r"(r3) : "r"(addr));
}
__device__ __forceinline__ void mma16816(float* d, const uint32_t* a, const uint32_t* b) {
    asm volatile(
        "mma.sync.aligned.m16n8k16.row.col.f32.bf16.bf16.f32 "
        "{%0,%1,%2,%3}, {%4,%5,%6,%7}, {%8,%9}, {%0,%1,%2,%3};"
        : "+f"(d[0]), "+f"(d[1]), "+f"(d[2]), "+f"(d[3])
        : "r"(a[0]), "r"(a[1]), "r"(a[2]), "r"(a[3]), "r"(b[0]), "r"(b[1]));
}
__device__ __forceinline__ float fast_exp2(float x) {
    float y;
    asm("ex2.approx.f32 %0, %1;" : "=f"(y) : "f"(x));
    return y;
}
__device__ __forceinline__ float fast_log(float x) {
    float y;
    asm("lg2.approx.f32 %0, %1;" : "=f"(y) : "f"(x));
    return y * LN2;
}

// cp.async one 64-wide K chunk (128B/row, swizzled) of A and B into a stage buffer
__device__ __forceinline__ void load_chunk(uint32_t s, const __nv_bfloat16* A,
                                           const __nv_bfloat16* B, int k0, int tid) {
    const uint32_t sa = s, sb = s + TILE_BYTES;
    #pragma unroll
    for (int i = 0; i < 4; i++) {
        const int idx = tid + i * 256;        // 0..1023
        const int r = idx >> 3, q = idx & 7;  // row 0..127, 16B seg 0..7
        CPA(SWADDR(sa, r, q), A + (size_t)r * DIM + k0 + q * 8);
        CPA(SWADDR(sb, r, q), B + (size_t)r * DIM + k0 + q * 8);
    }
}

__device__ __forceinline__ void tile_coords(int t, int& bi, int& bj) {
    int b = 0;
    while (t >= NBLK - b) { t -= NBLK - b; b++; }
    bi = b; bj = b + t;
}

// ============================ Fused persistent kernel ============================
__global__ __launch_bounds__(256, 2)
void sim_loss_mma(const float* __restrict__ emb, const int* __restrict__ lab32,
                  float* __restrict__ out) {
    extern __shared__ __align__(128) char SM[];
    const uint32_t sbase = smem_u32(SM);
    const int tid = threadIdx.x, wid = tid >> 5, lane = tid & 31;
    const int wm = wid >> 2, wn = wid & 3;   // warp grid 2 (M) x 4 (N)

    float* sRN = (float*)(SM + OFF_RN);
    float* sRD = (float*)(SM + OFF_RD);
    float* sCN = (float*)(SM + OFF_CN);
    float* sCD = (float*)(SM + OFF_CD);

    // ======== phase 0: normalize rows -> bf16, decode labels, zero accumulators ========
    {
        __shared__ int is64_s;
        if (tid < 32) {
            // 32 odd-word probes, in-bounds under either labels layout.
            // int64 layout => all zero; int32 => P(all zero) = 512^-32 ~ 0.
            const unsigned probe = __ballot_sync(0xffffffffu, lab32[2 * tid + 1] != 0);
            if (tid == 0) is64_s = (probe == 0u) ? 1 : 0;
        }
        __syncthreads();
        const bool is64 = (is64_s != 0);

        // one row per warp, strided over all CTAs (2368 warps, 8192 rows)
        for (int r = blockIdx.x * 8 + wid; r < NROWS; r += GRID * 8) {
            const float4* in = (const float4*)(emb + (size_t)r * DIM);
            float4 x[4];
            float ss = 0.0f;
            #pragma unroll
            for (int i = 0; i < 4; i++) {
                x[i] = in[lane + 32 * i];
                ss += x[i].x * x[i].x + x[i].y * x[i].y + x[i].z * x[i].z + x[i].w * x[i].w;
            }
            #pragma unroll
            for (int o = 16; o; o >>= 1) ss += __shfl_xor_sync(0xffffffffu, ss, o);
            const float inv = rsqrtf(ss);
            uint2* outp = (uint2*)(g_ebf + (size_t)r * DIM);
            #pragma unroll
            for (int i = 0; i < 4; i++) {
                __nv_bfloat162 p0 = __floats2bfloat162_rn(x[i].x * inv, x[i].y * inv);
                __nv_bfloat162 p1 = __floats2bfloat162_rn(x[i].z * inv, x[i].w * inv);
                uint2 v;
                v.x = *(uint32_t*)&p0; v.y = *(uint32_t*)&p1;
                outp[lane + 32 * i] = v;
            }
            if (lane == 0) {
                g_num[r] = 0.0f;
                g_den[r] = 0.0f;
                g_lab[r] = is64 ? lab32[2 * r] : lab32[r];
            }
        }

        // ---- device-wide barrier (all 296 CTAs co-resident) ----
        __threadfence();
        __syncthreads();
        if (tid == 0) {
            atomicAdd(&g_sync, 1u);
            while (*(volatile unsigned*)&g_sync < (unsigned)GRID) __nanosleep(64);
        }
        __syncthreads();
        __threadfence();
    }

    // ======== phase 1: persistent GEMM + fused epilogue ========
    int t = blockIdx.x;
    int bi, bj;
    tile_coords(t, bi, bj);
    const __nv_bfloat16* Ag = g_ebf + (size_t)bi * TM * DIM;
    const __nv_bfloat16* Bg = g_ebf + (size_t)bj * TN * DIM;

    // prologue: chunks 0,1 of first tile into buffers 0,1
    load_chunk(sbase + 0 * STAGE_BYTES, Ag, Bg, 0, tid); CPA_COMMIT();
    load_chunk(sbase + 1 * STAGE_BYTES, Ag, Bg, KC, tid); CPA_COMMIT();
    int wbuf = 2;   // next buffer to write (cycles 0..2 across tiles)
    int rbuf = 0;   // buffer of current compute chunk

    float acc[4][4][4];
    #pragma unroll
    for (int i = 0; i < 4; i++)
        #pragma unroll
        for (int j = 0; j < 4; j++)
            #pragma unroll
            for (int v = 0; v < 4; v++) acc[i][j][v] = 0.0f;

    while (true) {
        const int rowBase = bi * TM, colBase = bj * TN;
        const bool offDiag = (bi != bj);

        const int tn = t + GRID;
        const bool hasNext = (tn < NTILES);
        const __nv_bfloat16 *An = Ag, *Bn = Bg;
        int nbi = bi, nbj = bj;
        if (hasNext) {
            tile_coords(tn, nbi, nbj);
            An = g_ebf + (size_t)nbi * TM * DIM;
            Bn = g_ebf + (size_t)nbj * TN * DIM;
        }

        // ---- mainloop: 8 chunks of K=64, 3-stage cycle, prefetch distance 2 ----
        #pragma unroll 1
        for (int c = 0; c < NC; c++) {
            if (c == NC - 1 && !hasNext) { CPA_WAIT(0); } else { CPA_WAIT(1); }
            __syncthreads();

            // prefetch chunk c+2 into the buffer consumed at iteration c-1
            const int pc = c + STAGES - 1;   // c + 2
            if (pc < NC) {
                load_chunk(sbase + wbuf * STAGE_BYTES, Ag, Bg, pc * KC, tid);
                CPA_COMMIT();
                wbuf = (wbuf + 1 == STAGES) ? 0 : wbuf + 1;
            } else if (hasNext && pc - NC < STAGES - 1) {
                load_chunk(sbase + wbuf * STAGE_BYTES, An, Bn, (pc - NC) * KC, tid);
                CPA_COMMIT();
                wbuf = (wbuf + 1 == STAGES) ? 0 : wbuf + 1;
            }

            const uint32_t sa = sbase + rbuf * STAGE_BYTES;
            const uint32_t sb = sa + TILE_BYTES;
            rbuf = (rbuf + 1 == STAGES) ? 0 : rbuf + 1;

            #pragma unroll
            for (int ks = 0; ks < 4; ks++) {          // four k16 steps per 64-chunk
                uint32_t bfr[4][2];
                #pragma unroll
                for (int p = 0; p < 2; p++) {
                    const int nrow = wn * 32 + p * 16 + ((lane >> 4) << 3) + (lane & 7);
                    const int seg = ks * 2 + ((lane >> 3) & 1);
                    uint32_t r0, r1, r2, r3;
                    ldmx4(r0, r1, r2, r3, SWADDR(sb, nrow, seg));
                    bfr[2 * p][0] = r0; bfr[2 * p][1] = r1;
                    bfr[2 * p + 1][0] = r2; bfr[2 * p + 1][1] = r3;
                }
                #pragma unroll
                for (int mt = 0; mt < 4; mt++) {
                    const int arow = wm * 64 + mt * 16 + (lane & 15);
                    const int aseg = ks * 2 + (lane >> 4);
                    uint32_t afr[4];
                    ldmx4(afr[0], afr[1], afr[2], afr[3], SWADDR(sa, arow, aseg));
                    #pragma unroll
                    for (int nt = 0; nt < 4; nt++)
                        mma16816(acc[mt][nt], afr, bfr[nt]);
                }
            }
        }

        // ---- branch-specialized single-pass epilogue ----
        __syncthreads();
        if (tid < 128) { sRN[tid] = 0.0f; sRD[tid] = 0.0f; }
        else           { sCN[tid - 128] = 0.0f; sCD[tid - 128] = 0.0f; }
        __syncthreads();

        int liArr[8], ljArr[8];
        #pragma unroll
        for (int mt = 0; mt < 4; mt++)
            #pragma unroll
            for (int rh = 0; rh < 2; rh++)
                liArr[mt * 2 + rh] = g_lab[rowBase + wm * 64 + mt * 16 + rh * 8 + (lane >> 2)];
        #pragma unroll
        for (int nt = 0; nt < 4; nt++)
            #pragma unroll
            for (int ce = 0; ce < 2; ce++)
                ljArr[nt * 2 + ce] = g_lab[colBase + wn * 32 + nt * 8 + 2 * (lane & 3) + ce];

        if (offDiag) {
            // off-diagonal tile: gi != gj always -> no diag test; row + col fused.
            float cnum[8], cden[8];
            #pragma unroll
            for (int i = 0; i < 8; i++) { cnum[i] = 0.0f; cden[i] = 0.0f; }

            #pragma unroll
            for (int mt = 0; mt < 4; mt++) {
                #pragma unroll
                for (int rh = 0; rh < 2; rh++) {
                    const int rloc = wm * 64 + mt * 16 + rh * 8 + (lane >> 2);
                    const int li = liArr[mt * 2 + rh];
                    float rnum = 0.0f, rden = 0.0f;
                    #pragma unroll
                    for (int nt = 0; nt < 4; nt++) {
                        #pragma unroll
                        for (int ce = 0; ce < 2; ce++) {
                            const int j = nt * 2 + ce;
                            const float v = acc[mt][nt][rh * 2 + ce];
                            const float e = fast_exp2(v * INVT_LOG2E);
                            const bool pos = (li == ljArr[j]) && (v > 0.0f);
                            const float nu = pos ? e : 0.0f;
                            rden += e; rnum += nu;
                            cden[j] += e; cnum[j] += nu;
                        }
                    }
                    rnum += __shfl_xor_sync(0xffffffffu, rnum, 1);
                    rden += __shfl_xor_sync(0xffffffffu, rden, 1);
                    rnum += __shfl_xor_sync(0xffffffffu, rnum, 2);
                    rden += __shfl_xor_sync(0xffffffffu, rden, 2);
                    if ((lane & 3) == 0) {
                        atomicAdd(&sRD[rloc], rden);
                        if (rnum != 0.0f) atomicAdd(&sRN[rloc], rnum);
                    }
                }
            }
            #pragma unroll
            for (int nt = 0; nt < 4; nt++) {
                #pragma unroll
                for (int ce = 0; ce < 2; ce++) {
                    const int j = nt * 2 + ce;
                    const int cloc = wn * 32 + nt * 8 + 2 * (lane & 3) + ce;
                    float cn = cnum[j], cd = cden[j];
                    cn += __shfl_xor_sync(0xffffffffu, cn, 4);
                    cd += __shfl_xor_sync(0xffffffffu, cd, 4);
                    cn += __shfl_xor_sync(0xffffffffu, cn, 8);
                    cd += __shfl_xor_sync(0xffffffffu, cd, 8);
                    cn += __shfl_xor_sync(0xffffffffu, cn, 16);
                    cd += __shfl_xor_sync(0xffffffffu, cd, 16);
                    if (lane < 4) {   // one writer per lane&3 group
                        atomicAdd(&sCD[cloc], cd);
                        if (cn != 0.0f) atomicAdd(&sCN[cloc], cn);
                    }
                }
            }
        } else {
            // diagonal tile: keep diag test, no column accumulation.
            #pragma unroll
            for (int mt = 0; mt < 4; mt++) {
                #pragma unroll
                for (int rh = 0; rh < 2; rh++) {
                    const int rloc = wm * 64 + mt * 16 + rh * 8 + (lane >> 2);
                    const int gi = rowBase + rloc;
                    const int li = liArr[mt * 2 + rh];
                    float rnum = 0.0f, rden = 0.0f;
                    #pragma unroll
                    for (int nt = 0; nt < 4; nt++) {
                        #pragma unroll
                        for (int ce = 0; ce < 2; ce++) {
                            const int cloc = wn * 32 + nt * 8 + 2 * (lane & 3) + ce;
                            const float v = acc[mt][nt][rh * 2 + ce];
                            const float e = fast_exp2(v * INVT_LOG2E);
                            const bool diag = (gi == colBase + cloc);
                            const bool pos = !diag && (li == ljArr[nt * 2 + ce]) && (v > 0.0f);
                            rden += diag ? 0.0f : e;
                            rnum += pos ? e : 0.0f;
                        }
                    }
                    rnum += __shfl_xor_sync(0xffffffffu, rnum, 1);
                    rden += __shfl_xor_sync(0xffffffffu, rden, 1);
                    rnum += __shfl_xor_sync(0xffffffffu, rnum, 2);
                    rden += __shfl_xor_sync(0xffffffffu, rden, 2);
                    if ((lane & 3) == 0) {
                        atomicAdd(&sRD[rloc], rden);
                        if (rnum != 0.0f) atomicAdd(&sRN[rloc], rnum);
                    }
                }
            }
        }
        __syncthreads();

        if (tid < 128) {
            atomicAdd(&g_den[rowBase + tid], sRD[tid]);
            const float rn = sRN[tid];
            if (rn != 0.0f) atomicAdd(&g_num[rowBase + tid], rn);
        } else if (offDiag) {
            const int i = tid - 128;
            atomicAdd(&g_den[colBase + i], sCD[i]);
            const float cn = sCN[i];
            if (cn != 0.0f) atomicAdd(&g_num[colBase + i], cn);
        }

        #pragma unroll
        for (int i = 0; i < 4; i++)
            #pragma unroll
            for (int j = 0; j < 4; j++)
                #pragma unroll
                for (int v = 0; v < 4; v++) acc[i][j][v] = 0.0f;

        if (!hasNext) break;
        t = tn; bi = nbi; bj = nbj; Ag = An; Bg = Bn;
    }

    // ---- grid completion: last CTA computes the final loss, resets counters ----
    __syncthreads();
    __threadfence();
    __shared__ int isLast;
    if (tid == 0) isLast = (atomicAdd(&g_done, 1u) == (unsigned)(GRID - 1)) ? 1 : 0;
    __syncthreads();
    if (isLast) {
        float sum = 0.0f;
        int cnt = 0;
        for (int i = tid; i < NROWS; i += 256) {
            const float nu = g_num[i];
            const float de = g_den[i];
            if (nu > 0.0f && de > 0.0f) {
                sum += fast_log((de + 1e-8f) / nu);
                cnt++;
            }
        }
        #pragma unroll
        for (int o = 16; o; o >>= 1) {
            sum += __shfl_xor_sync(0xffffffffu, sum, o);
            cnt += __shfl_xor_sync(0xffffffffu, cnt, o);
        }
        if (lane == 0) { sRN[wid] = sum; ((int*)sRD)[wid] = cnt; }
        __syncthreads();
        if (tid == 0) {
            float s = 0.0f; int c = 0;
            #pragma unroll
            for (int i = 0; i < 8; i++) { s += sRN[i]; c += ((int*)sRD)[i]; }
            out[0] = (c > 0) ? fabsf(s / (float)c) : 0.0f;
            // reset device barrier state for the next graph replay
            g_sync = 0u;
            g_done = 0u;
        }
    }
}

extern "C" void kernel_launch(void* const* d_in, const int* in_sizes, int n_in,
                              void* d_out, int out_size) {
    const float* emb = (const float*)d_in[0];
    const int* lab32 = (const int*)d_in[1];
    float* out = (float*)d_out;

    cudaFuncSetAttribute(sim_loss_mma, cudaFuncAttributeMaxDynamicSharedMemorySize, SMEM_BYTES);

    sim_loss_mma<<<GRID, 256, SMEM_BYTES>>>(emb, lab32, out);
}